// round 1
// baseline (speedup 1.0000x reference)
#include <cuda_runtime.h>

#define N_ROWS 1024
#define X1D 256
#define X2D 128
#define HID 256
#define R 8               // rows per block
#define KC 64             // k-chunk staged in smem
#define NTHR 256
#define NBLK (N_ROWS / R) // 128

// column stats of x2 (means of x2 and x2^2), computed once per launch
__device__ float g_x2m[X2D];
__device__ float g_x2sq[X2D];

// ---------------------------------------------------------------------------
// Kernel 1: x2 column stats + zero the output scalar
// blockDim = 1024: thread = s*128 + c ; each (s,c) sums 128 rows of column c
// ---------------------------------------------------------------------------
__global__ void __launch_bounds__(1024) club_stats_kernel(
    const float* __restrict__ x2, float* __restrict__ out)
{
    __shared__ float sm[8][128];
    __shared__ float sq[8][128];
    int t = threadIdx.x;
    int c = t & 127;
    int s = t >> 7;
    float a = 0.f, b = 0.f;
    #pragma unroll 4
    for (int r = s; r < N_ROWS; r += 8) {
        float v = x2[r * X2D + c];
        a += v;
        b += v * v;
    }
    sm[s][c] = a;
    sq[s][c] = b;
    __syncthreads();
    if (t < 128) {
        float ma = 0.f, mb = 0.f;
        #pragma unroll
        for (int k = 0; k < 8; k++) { ma += sm[k][t]; mb += sq[k][t]; }
        g_x2m[t]  = ma * (1.0f / N_ROWS);
        g_x2sq[t] = mb * (1.0f / N_ROWS);
        if (t == 0) out[0] = 0.0f;
    }
}

// ---------------------------------------------------------------------------
// Kernel 2: fused 3-layer MLP + CLUB epilogue.
// Each block: 8 rows. Thread j owns output column j of every layer.
// Activations live transposed in smem (buf[k][r]) so the inner loop reads
// them with two 128-bit broadcast LDS per k. Weights staged in 64-row chunks.
// ---------------------------------------------------------------------------
__global__ void __launch_bounds__(NTHR) club_mlp_kernel(
    const float* __restrict__ x1, const float* __restrict__ x2,
    const float* __restrict__ W1, const float* __restrict__ b1,
    const float* __restrict__ W2, const float* __restrict__ b2,
    const float* __restrict__ W3, const float* __restrict__ b3,
    float* __restrict__ out)
{
    extern __shared__ float smem[];
    float* s_w   = smem;                    // KC*256      = 16384 floats
    float* bufA  = s_w  + KC * HID;         // 256*8       =  2048
    float* bufB  = bufA + HID * R;          // 256*8       =  2048
    float* s_x2  = bufB + HID * R;          // 8*128       =  1024
    float* s_red = s_x2 + R * X2D;          // 256

    const int j    = threadIdx.x;
    const int row0 = blockIdx.x * R;

    // load x1 tile transposed: bufA[k*R + r] = x1[row0+r][k]
    #pragma unroll
    for (int r = 0; r < R; r++) {
        bufA[j * R + r] = x1[(row0 + r) * X1D + j];
    }
    // load x2 tile: s_x2[r*128 + d]
    for (int idx = j; idx < R * X2D; idx += NTHR) {
        s_x2[idx] = x2[row0 * X2D + idx];
    }
    __syncthreads();

    auto layer = [&](const float* __restrict__ W, const float* __restrict__ B,
                     const float* __restrict__ inb, float* __restrict__ outb,
                     int act) {
        float acc[R];
        #pragma unroll
        for (int r = 0; r < R; r++) acc[r] = 0.f;

        for (int k0 = 0; k0 < HID; k0 += KC) {
            // stage W[k0..k0+KC) x [0..256) into smem, fully coalesced
            const float4* wg = reinterpret_cast<const float4*>(W + k0 * HID);
            float4* ws = reinterpret_cast<float4*>(s_w);
            #pragma unroll
            for (int i = 0; i < (KC * HID / 4) / NTHR; i++)   // 16 iters
                ws[j + i * NTHR] = wg[j + i * NTHR];
            __syncthreads();

            #pragma unroll 8
            for (int kk = 0; kk < KC; kk++) {
                float w = s_w[kk * HID + j];
                const float4* iv =
                    reinterpret_cast<const float4*>(inb + (k0 + kk) * R);
                float4 a0 = iv[0];
                float4 a1 = iv[1];
                acc[0] = fmaf(a0.x, w, acc[0]);
                acc[1] = fmaf(a0.y, w, acc[1]);
                acc[2] = fmaf(a0.z, w, acc[2]);
                acc[3] = fmaf(a0.w, w, acc[3]);
                acc[4] = fmaf(a1.x, w, acc[4]);
                acc[5] = fmaf(a1.y, w, acc[5]);
                acc[6] = fmaf(a1.z, w, acc[6]);
                acc[7] = fmaf(a1.w, w, acc[7]);
            }
            __syncthreads();  // s_w reused next chunk
        }

        float bb = B[j];
        #pragma unroll
        for (int r = 0; r < R; r++) {
            float v = acc[r] + bb;
            v = act ? tanhf(v) : fmaxf(v, 0.f);
            outb[j * R + r] = v;
        }
        __syncthreads();
    };

    layer(W1, b1, bufA, bufB, 0);
    layer(W2, b2, bufB, bufA, 0);
    layer(W3, b3, bufA, bufB, 1);   // g (tanh) in bufB, transposed [col][r]

    // Epilogue: pos - neg with the closed-form negative term.
    // pos-neg = -0.5*iv*( x2i^2 - 2*mu*x2i + 2*mu*E[x2] - E[x2^2] )
    float part = 0.f;
    if (j < X2D) {
        const int d = j;
        const float x2m = g_x2m[d];
        const float x2s = g_x2sq[d];
        #pragma unroll
        for (int r = 0; r < R; r++) {
            float mu = bufB[d * R + r];
            float lv = bufB[(X2D + d) * R + r];
            float iv = __expf(-lv);
            float xi = s_x2[r * X2D + d];
            float term = xi * xi - 2.f * mu * xi + 2.f * mu * x2m - x2s;
            part += -0.5f * iv * term;
        }
    }
    s_red[j] = part;
    __syncthreads();
    #pragma unroll
    for (int off = 128; off > 0; off >>= 1) {
        if (j < off) s_red[j] += s_red[j + off];
        __syncthreads();
    }
    if (j == 0) atomicAdd(out, s_red[0] * (1.0f / N_ROWS));
}

// ---------------------------------------------------------------------------

extern "C" void kernel_launch(void* const* d_in, const int* in_sizes, int n_in,
                              void* d_out, int out_size)
{
    const float* x1 = (const float*)d_in[0];
    const float* x2 = (const float*)d_in[1];
    const float* W1 = (const float*)d_in[2];
    const float* b1 = (const float*)d_in[3];
    const float* W2 = (const float*)d_in[4];
    const float* b2 = (const float*)d_in[5];
    const float* W3 = (const float*)d_in[6];
    const float* b3 = (const float*)d_in[7];
    float* out = (float*)d_out;

    const int smem_bytes = (KC * HID + 2 * HID * R + R * X2D + NTHR) * sizeof(float);
    cudaFuncSetAttribute(club_mlp_kernel,
                         cudaFuncAttributeMaxDynamicSharedMemorySize, smem_bytes);

    club_stats_kernel<<<1, 1024>>>(x2, out);
    club_mlp_kernel<<<NBLK, NTHR, smem_bytes>>>(x1, x2, W1, b1, W2, b2, W3, b3, out);
}

// round 2
// speedup vs baseline: 1.8931x; 1.8931x over previous
#include <cuda_runtime.h>

#define N_ROWS 1024
#define X1D 256
#define X2D 128
#define HID 256
#define R 8                 // rows per block
#define NTHR 1024           // 4 k-groups x 256 output columns
#define KSPLIT 4
#define KPER (HID / KSPLIT) // 64
#define NBLK (N_ROWS / R)   // 128
#define SBLK 8              // stats blocks

// per-block partial column sums of x2 and x2^2 (8 blocks x 128 cols)
__device__ float g_part_m[SBLK * X2D];
__device__ float g_part_s[SBLK * X2D];

// ---------------------------------------------------------------------------
// Kernel 1: partial x2 column stats (8 blocks, 128 rows each) + zero out[0]
// ---------------------------------------------------------------------------
__global__ void __launch_bounds__(1024) club_stats_kernel(
    const float* __restrict__ x2, float* __restrict__ out)
{
    __shared__ float sm[8][128];
    __shared__ float sq[8][128];
    int t = threadIdx.x;
    int c = t & 127;
    int s = t >> 7;
    int r0 = blockIdx.x * 128 + s * 16;
    float a = 0.f, b = 0.f;
    #pragma unroll
    for (int i = 0; i < 16; i++) {
        float v = x2[(r0 + i) * X2D + c];
        a += v;
        b += v * v;
    }
    sm[s][c] = a;
    sq[s][c] = b;
    __syncthreads();
    if (t < 128) {
        float ma = 0.f, mb = 0.f;
        #pragma unroll
        for (int k = 0; k < 8; k++) { ma += sm[k][t]; mb += sq[k][t]; }
        g_part_m[blockIdx.x * X2D + t] = ma;
        g_part_s[blockIdx.x * X2D + t] = mb;
    }
    if (blockIdx.x == 0 && t == 0) out[0] = 0.0f;
}

// ---------------------------------------------------------------------------
// Kernel 2: fused 3-layer MLP + CLUB epilogue.
// 1024 threads: j = t&255 owns output column j, h = t>>8 owns k-range
// [h*64, h*64+64). Weights read straight from L2 (LDG, coalesced over j).
// Activations transposed in smem; partials reduced through smem per layer.
// ---------------------------------------------------------------------------
__global__ void __launch_bounds__(NTHR) club_mlp_kernel(
    const float* __restrict__ x1, const float* __restrict__ x2,
    const float* __restrict__ W1, const float* __restrict__ b1,
    const float* __restrict__ W2, const float* __restrict__ b2,
    const float* __restrict__ W3, const float* __restrict__ b3,
    float* __restrict__ out)
{
    __shared__ float bufA[HID * R];                 // 2048
    __shared__ float bufB[HID * R];                 // 2048
    __shared__ float s_x2[R * X2D];                 // 1024
    __shared__ float s_part[(KSPLIT - 1) * R * HID];// 6144 (transposed, conflict-free)
    __shared__ float s_m[X2D];
    __shared__ float s_s[X2D];
    __shared__ float s_red[32];

    const int t    = threadIdx.x;
    const int j    = t & 255;
    const int h    = t >> 8;
    const int row0 = blockIdx.x * R;

    // stage x1 tile transposed: bufA[c*R + r] = x1[row0+r][c]
    // 1024 threads cover 4 rows x 256 cols per pass, 2 passes
    {
        int c = t & 255, rr = t >> 8;
        #pragma unroll
        for (int p = 0; p < 2; p++) {
            int r = rr + p * 4;
            bufA[c * R + r] = x1[(row0 + r) * X1D + c];
        }
    }
    // stage x2 tile: 1024 floats, one per thread
    s_x2[t] = x2[row0 * X2D + t];

    // combine global stats partials (needs kernel 1 done; same stream => yes)
    if (t < X2D) {
        float ma = 0.f, mb = 0.f;
        #pragma unroll
        for (int b = 0; b < SBLK; b++) {
            ma += g_part_m[b * X2D + t];
            mb += g_part_s[b * X2D + t];
        }
        s_m[t] = ma * (1.0f / N_ROWS);
        s_s[t] = mb * (1.0f / N_ROWS);
    }
    __syncthreads();

    auto layer = [&](const float* __restrict__ W, const float* __restrict__ B,
                     const float* __restrict__ inb, float* __restrict__ outb,
                     int act) {
        float acc[R];
        #pragma unroll
        for (int r = 0; r < R; r++) acc[r] = 0.f;

        const float* wp = W + (h * KPER) * HID + j;   // coalesced over j
        const float* ip = inb + (h * KPER) * R;       // warp-uniform (broadcast)

        #pragma unroll 16
        for (int kk = 0; kk < KPER; kk++) {
            float w = __ldg(wp + kk * HID);
            const float4* iv = reinterpret_cast<const float4*>(ip + kk * R);
            float4 a0 = iv[0];
            float4 a1 = iv[1];
            acc[0] = fmaf(a0.x, w, acc[0]);
            acc[1] = fmaf(a0.y, w, acc[1]);
            acc[2] = fmaf(a0.z, w, acc[2]);
            acc[3] = fmaf(a0.w, w, acc[3]);
            acc[4] = fmaf(a1.x, w, acc[4]);
            acc[5] = fmaf(a1.y, w, acc[5]);
            acc[6] = fmaf(a1.z, w, acc[6]);
            acc[7] = fmaf(a1.w, w, acc[7]);
        }

        if (h > 0) {
            // transposed store: consecutive j -> consecutive banks
            #pragma unroll
            for (int r = 0; r < R; r++)
                s_part[((h - 1) * R + r) * HID + j] = acc[r];
        }
        __syncthreads();

        if (h == 0) {
            #pragma unroll
            for (int g = 0; g < KSPLIT - 1; g++)
                #pragma unroll
                for (int r = 0; r < R; r++)
                    acc[r] += s_part[(g * R + r) * HID + j];
            float bb = B[j];
            #pragma unroll
            for (int r = 0; r < R; r++) {
                float v = acc[r] + bb;
                v = act ? tanhf(v) : fmaxf(v, 0.f);
                outb[j * R + r] = v;
            }
        }
        __syncthreads();
    };

    layer(W1, b1, bufA, bufB, 0);
    layer(W2, b2, bufB, bufA, 0);
    layer(W3, b3, bufA, bufB, 1);   // g (tanh) in bufB, transposed [col][r]

    // Epilogue: one (row, dim) pair per thread.
    // pos-neg = -0.5*iv*( xi^2 - 2*mu*xi + 2*mu*E[x2] - E[x2^2] )
    float part;
    {
        int d = t & 127;
        int r = t >> 7;
        float mu = bufB[d * R + r];
        float lv = bufB[(X2D + d) * R + r];
        float iv = __expf(-lv);
        float xi = s_x2[r * X2D + d];
        float term = xi * xi - 2.f * mu * xi + 2.f * mu * s_m[d] - s_s[d];
        part = -0.5f * iv * term;
    }
    // block reduction
    #pragma unroll
    for (int off = 16; off > 0; off >>= 1)
        part += __shfl_xor_sync(0xffffffffu, part, off);
    if ((t & 31) == 0) s_red[t >> 5] = part;
    __syncthreads();
    if (t < 32) {
        float v = s_red[t];
        #pragma unroll
        for (int off = 16; off > 0; off >>= 1)
            v += __shfl_xor_sync(0xffffffffu, v, off);
        if (t == 0) atomicAdd(out, v * (1.0f / N_ROWS));
    }
}

// ---------------------------------------------------------------------------

extern "C" void kernel_launch(void* const* d_in, const int* in_sizes, int n_in,
                              void* d_out, int out_size)
{
    const float* x1 = (const float*)d_in[0];
    const float* x2 = (const float*)d_in[1];
    const float* W1 = (const float*)d_in[2];
    const float* b1 = (const float*)d_in[3];
    const float* W2 = (const float*)d_in[4];
    const float* b2 = (const float*)d_in[5];
    const float* W3 = (const float*)d_in[6];
    const float* b3 = (const float*)d_in[7];
    float* out = (float*)d_out;

    club_stats_kernel<<<SBLK, 1024>>>(x2, out);
    club_mlp_kernel<<<NBLK, NTHR>>>(x1, x2, W1, b1, W2, b2, W3, b3, out);
}

// round 3
// speedup vs baseline: 2.0468x; 1.0812x over previous
#include <cuda_runtime.h>

#define N_ROWS 1024
#define X1D 256
#define X2D 128
#define HID 256
#define R 8                 // rows per block
#define NTHR 1024
#define NG 16               // k-groups
#define KPER (HID / NG)     // 16
#define CT 64               // col-threads per group (4 cols each)
#define NBLK (N_ROWS / R)   // 128
#define SBLK 8              // stats blocks

// per-block partial column sums of x2 and x2^2
__device__ float g_part_m[SBLK * X2D];
__device__ float g_part_s[SBLK * X2D];

// ---------------------------------------------------------------------------
// Kernel 1: partial x2 column stats + zero out[0]
// ---------------------------------------------------------------------------
__global__ void __launch_bounds__(1024) club_stats_kernel(
    const float* __restrict__ x2, float* __restrict__ out)
{
    __shared__ float sm[8][128];
    __shared__ float sq[8][128];
    int t = threadIdx.x;
    int c = t & 127;
    int s = t >> 7;
    int r0 = blockIdx.x * 128 + s * 16;
    float a = 0.f, b = 0.f;
    #pragma unroll
    for (int i = 0; i < 16; i++) {
        float v = x2[(r0 + i) * X2D + c];
        a += v;
        b += v * v;
    }
    sm[s][c] = a;
    sq[s][c] = b;
    __syncthreads();
    if (t < 128) {
        float ma = 0.f, mb = 0.f;
        #pragma unroll
        for (int k = 0; k < 8; k++) { ma += sm[k][t]; mb += sq[k][t]; }
        g_part_m[blockIdx.x * X2D + t] = ma;
        g_part_s[blockIdx.x * X2D + t] = mb;
    }
    if (blockIdx.x == 0 && t == 0) out[0] = 0.0f;
}

// ---------------------------------------------------------------------------
// Kernel 2: fused 3-layer MLP + CLUB epilogue.
// 1024 threads = 16 k-groups (h = t>>6) x 64 col-threads (c4 = t&63, 4 cols
// each). Per k-step: 1 LDG.128 (weights) + 2 LDS.128 (8 transposed act rows)
// feeding 32 FFMA. Per-group partials go to smem; all 1024 threads reduce.
// ---------------------------------------------------------------------------
__global__ void __launch_bounds__(NTHR, 1) club_mlp_kernel(
    const float* __restrict__ x1, const float* __restrict__ x2,
    const float* __restrict__ W1, const float* __restrict__ b1,
    const float* __restrict__ W2, const float* __restrict__ b2,
    const float* __restrict__ W3, const float* __restrict__ b3,
    float* __restrict__ out)
{
    extern __shared__ float smem[];
    float* s_part = smem;                   // NG*R*HID = 32768 floats (128KB)
    float* bufA   = s_part + NG * R * HID;  // 2048
    float* bufB   = bufA + HID * R;         // 2048
    float* s_x2   = bufB + HID * R;         // 1024
    float* s_m    = s_x2 + R * X2D;         // 128
    float* s_s    = s_m + X2D;              // 128
    float* s_red  = s_s + X2D;              // 32

    const int t    = threadIdx.x;
    const int c4   = t & (CT - 1);          // column quad: cols 4*c4..4*c4+3
    const int h    = t >> 6;                // k-group
    const int row0 = blockIdx.x * R;

    // stage x1 tile transposed: bufA[c*R + r] = x1[row0+r][c]
    {
        int c = t & 255, rr = t >> 8;
        #pragma unroll
        for (int p = 0; p < 2; p++) {
            int r = rr + p * 4;
            bufA[c * R + r] = x1[(row0 + r) * X1D + c];
        }
    }
    s_x2[t] = x2[row0 * X2D + t];

    if (t < X2D) {
        float ma = 0.f, mb = 0.f;
        #pragma unroll
        for (int b = 0; b < SBLK; b++) {
            ma += g_part_m[b * X2D + t];
            mb += g_part_s[b * X2D + t];
        }
        s_m[t] = ma * (1.0f / N_ROWS);
        s_s[t] = mb * (1.0f / N_ROWS);
    }
    __syncthreads();

    auto layer = [&](const float* __restrict__ W, const float* __restrict__ B,
                     const float* __restrict__ inb, float* __restrict__ outb,
                     int act) {
        float4 acc[R];
        #pragma unroll
        for (int r = 0; r < R; r++) acc[r] = make_float4(0.f, 0.f, 0.f, 0.f);

        const float4* wp = reinterpret_cast<const float4*>(W + (h * KPER) * HID) + c4;
        const float4* ip = reinterpret_cast<const float4*>(inb + (h * KPER) * R);

        #pragma unroll
        for (int kk = 0; kk < KPER; kk++) {
            float4 w  = __ldg(wp + kk * (HID / 4));
            float4 a0 = ip[kk * 2];
            float4 a1 = ip[kk * 2 + 1];
            acc[0].x = fmaf(a0.x, w.x, acc[0].x); acc[0].y = fmaf(a0.x, w.y, acc[0].y);
            acc[0].z = fmaf(a0.x, w.z, acc[0].z); acc[0].w = fmaf(a0.x, w.w, acc[0].w);
            acc[1].x = fmaf(a0.y, w.x, acc[1].x); acc[1].y = fmaf(a0.y, w.y, acc[1].y);
            acc[1].z = fmaf(a0.y, w.z, acc[1].z); acc[1].w = fmaf(a0.y, w.w, acc[1].w);
            acc[2].x = fmaf(a0.z, w.x, acc[2].x); acc[2].y = fmaf(a0.z, w.y, acc[2].y);
            acc[2].z = fmaf(a0.z, w.z, acc[2].z); acc[2].w = fmaf(a0.z, w.w, acc[2].w);
            acc[3].x = fmaf(a0.w, w.x, acc[3].x); acc[3].y = fmaf(a0.w, w.y, acc[3].y);
            acc[3].z = fmaf(a0.w, w.z, acc[3].z); acc[3].w = fmaf(a0.w, w.w, acc[3].w);
            acc[4].x = fmaf(a1.x, w.x, acc[4].x); acc[4].y = fmaf(a1.x, w.y, acc[4].y);
            acc[4].z = fmaf(a1.x, w.z, acc[4].z); acc[4].w = fmaf(a1.x, w.w, acc[4].w);
            acc[5].x = fmaf(a1.y, w.x, acc[5].x); acc[5].y = fmaf(a1.y, w.y, acc[5].y);
            acc[5].z = fmaf(a1.y, w.z, acc[5].z); acc[5].w = fmaf(a1.y, w.w, acc[5].w);
            acc[6].x = fmaf(a1.z, w.x, acc[6].x); acc[6].y = fmaf(a1.z, w.y, acc[6].y);
            acc[6].z = fmaf(a1.z, w.z, acc[6].z); acc[6].w = fmaf(a1.z, w.w, acc[6].w);
            acc[7].x = fmaf(a1.w, w.x, acc[7].x); acc[7].y = fmaf(a1.w, w.y, acc[7].y);
            acc[7].z = fmaf(a1.w, w.z, acc[7].z); acc[7].w = fmaf(a1.w, w.w, acc[7].w);
        }

        // store partials: s_part[h][r][col], float4 over cols — coalesced STS.128
        float4* pp = reinterpret_cast<float4*>(s_part) + h * (R * HID / 4) + c4;
        #pragma unroll
        for (int r = 0; r < R; r++) pp[r * (HID / 4)] = acc[r];
        __syncthreads();

        // all-thread reduction: 2048 outputs, 2 per thread, 16 adds each
        #pragma unroll
        for (int p = 0; p < 2; p++) {
            int o = t + p * NTHR;        // o = r*256 + col
            float v = 0.f;
            #pragma unroll
            for (int g = 0; g < NG; g++) v += s_part[g * (R * HID) + o];
            int col = o & 255;
            int r   = o >> 8;
            v += B[col];
            v = act ? tanhf(v) : fmaxf(v, 0.f);
            outb[col * R + r] = v;
        }
        __syncthreads();
    };

    layer(W1, b1, bufA, bufB, 0);
    layer(W2, b2, bufB, bufA, 0);
    layer(W3, b3, bufA, bufB, 1);   // g (tanh) in bufB, transposed [col][r]

    // Epilogue: pos-neg = -0.5*iv*( xi^2 - 2*mu*xi + 2*mu*E[x2] - E[x2^2] )
    float part;
    {
        int d = t & 127;
        int r = t >> 7;
        float mu = bufB[d * R + r];
        float lv = bufB[(X2D + d) * R + r];
        float iv = __expf(-lv);
        float xi = s_x2[r * X2D + d];
        float term = xi * xi - 2.f * mu * xi + 2.f * mu * s_m[d] - s_s[d];
        part = -0.5f * iv * term;
    }
    #pragma unroll
    for (int off = 16; off > 0; off >>= 1)
        part += __shfl_xor_sync(0xffffffffu, part, off);
    if ((t & 31) == 0) s_red[t >> 5] = part;
    __syncthreads();
    if (t < 32) {
        float v = s_red[t];
        #pragma unroll
        for (int off = 16; off > 0; off >>= 1)
            v += __shfl_xor_sync(0xffffffffu, v, off);
        if (t == 0) atomicAdd(out, v * (1.0f / N_ROWS));
    }
}

// ---------------------------------------------------------------------------

extern "C" void kernel_launch(void* const* d_in, const int* in_sizes, int n_in,
                              void* d_out, int out_size)
{
    const float* x1 = (const float*)d_in[0];
    const float* x2 = (const float*)d_in[1];
    const float* W1 = (const float*)d_in[2];
    const float* b1 = (const float*)d_in[3];
    const float* W2 = (const float*)d_in[4];
    const float* b2 = (const float*)d_in[5];
    const float* W3 = (const float*)d_in[6];
    const float* b3 = (const float*)d_in[7];
    float* out = (float*)d_out;

    const int smem_bytes =
        (NG * R * HID + 2 * HID * R + R * X2D + 2 * X2D + 32) * sizeof(float);
    static int attr_set = 0;
    if (!attr_set) {
        cudaFuncSetAttribute(club_mlp_kernel,
                             cudaFuncAttributeMaxDynamicSharedMemorySize,
                             smem_bytes);
        attr_set = 1;
    }

    club_stats_kernel<<<SBLK, 1024>>>(x2, out);
    club_mlp_kernel<<<NBLK, NTHR, smem_bytes>>>(x1, x2, W1, b1, W2, b2, W3, b3, out);
}

// round 4
// speedup vs baseline: 2.2752x; 1.1116x over previous
#include <cuda_runtime.h>

#define N_ROWS 1024
#define X1D 256
#define X2D 128
#define HID 256
#define R 8                 // rows per block
#define NTHR 1024
#define NG 16               // k-groups
#define KPER (HID / NG)     // 16
#define CT 64               // col-threads per group (4 cols each)
#define NBLK (N_ROWS / R)   // 128
#define SBLK 8              // stats blocks

typedef unsigned long long u64;

__device__ __forceinline__ u64 bcast2(float w) {
    u64 d; asm("mov.b64 %0, {%1, %1};" : "=l"(d) : "f"(w)); return d;
}
__device__ __forceinline__ u64 ffma2(u64 a, u64 b, u64 c) {
    u64 d; asm("fma.rn.f32x2 %0, %1, %2, %3;" : "=l"(d) : "l"(a), "l"(b), "l"(c));
    return d;
}
__device__ __forceinline__ u64 fadd2(u64 a, u64 b) {
    u64 d; asm("add.rn.f32x2 %0, %1, %2;" : "=l"(d) : "l"(a), "l"(b));
    return d;
}
__device__ __forceinline__ void unpack2(float& lo, float& hi, u64 v) {
    asm("mov.b64 {%0, %1}, %2;" : "=f"(lo), "=f"(hi) : "l"(v));
}

// per-block partial column sums of x2 and x2^2
__device__ float g_part_m[SBLK * X2D];
__device__ float g_part_s[SBLK * X2D];

// ---------------------------------------------------------------------------
// Kernel 1: partial x2 column stats + zero out[0]
// ---------------------------------------------------------------------------
__global__ void __launch_bounds__(1024) club_stats_kernel(
    const float* __restrict__ x2, float* __restrict__ out)
{
    __shared__ float sm[8][128];
    __shared__ float sq[8][128];
    int t = threadIdx.x;
    int c = t & 127;
    int s = t >> 7;
    int r0 = blockIdx.x * 128 + s * 16;
    float a = 0.f, b = 0.f;
    #pragma unroll
    for (int i = 0; i < 16; i++) {
        float v = x2[(r0 + i) * X2D + c];
        a += v;
        b += v * v;
    }
    sm[s][c] = a;
    sq[s][c] = b;
    __syncthreads();
    if (t < 128) {
        float ma = 0.f, mb = 0.f;
        #pragma unroll
        for (int k = 0; k < 8; k++) { ma += sm[k][t]; mb += sq[k][t]; }
        g_part_m[blockIdx.x * X2D + t] = ma;
        g_part_s[blockIdx.x * X2D + t] = mb;
    }
    if (blockIdx.x == 0 && t == 0) out[0] = 0.0f;
}

// ---------------------------------------------------------------------------
// Kernel 2: fused 3-layer MLP + CLUB epilogue, packed f32x2 math.
// 1024 threads = 16 k-groups x 64 col-threads (4 cols each). Activations
// transposed in smem so row-pairs are aligned u64 packs. Per k-step:
// 1 LDG.128 (w) + 4 mov.b64 bcast + 2 LDS.128 (8 rows) + 16 FFMA2.
// ---------------------------------------------------------------------------
__global__ void __launch_bounds__(NTHR, 1) club_mlp_kernel(
    const float* __restrict__ x1, const float* __restrict__ x2,
    const float* __restrict__ W1, const float* __restrict__ b1,
    const float* __restrict__ W2, const float* __restrict__ b2,
    const float* __restrict__ W3, const float* __restrict__ b3,
    float* __restrict__ out)
{
    extern __shared__ float smem[];
    float* s_part = smem;                   // NG*R*HID = 32768 floats (128KB)
    float* bufA   = s_part + NG * R * HID;  // 2048
    float* bufB   = bufA + HID * R;         // 2048
    float* s_x2   = bufB + HID * R;         // 1024
    float* s_m    = s_x2 + R * X2D;         // 128
    float* s_s    = s_m + X2D;              // 128
    float* s_red  = s_s + X2D;              // 32

    const int t    = threadIdx.x;
    const int c4   = t & (CT - 1);          // column quad: cols 4*c4..4*c4+3
    const int h    = t >> 6;                // k-group
    const int row0 = blockIdx.x * R;

    // stage x1 tile transposed: bufA[c*R + r] = x1[row0+r][c]
    {
        int c = t & 255, rr = t >> 8;
        #pragma unroll
        for (int p = 0; p < 2; p++) {
            int r = rr + p * 4;
            bufA[c * R + r] = x1[(row0 + r) * X1D + c];
        }
    }
    s_x2[t] = x2[row0 * X2D + t];

    if (t < X2D) {
        float ma = 0.f, mb = 0.f;
        #pragma unroll
        for (int b = 0; b < SBLK; b++) {
            ma += g_part_m[b * X2D + t];
            mb += g_part_s[b * X2D + t];
        }
        s_m[t] = ma * (1.0f / N_ROWS);
        s_s[t] = mb * (1.0f / N_ROWS);
    }
    __syncthreads();

    auto layer = [&](const float* __restrict__ W, const float* __restrict__ B,
                     const float* __restrict__ inb, float* __restrict__ outb,
                     int act) {
        // acc[pair][col]: pair p holds rows (2p, 2p+1) packed as f32x2
        u64 acc[4][4];
        #pragma unroll
        for (int p = 0; p < 4; p++)
            #pragma unroll
            for (int c = 0; c < 4; c++) acc[p][c] = 0ULL;

        const float4* wp =
            reinterpret_cast<const float4*>(W + (h * KPER) * HID) + c4;
        const ulonglong2* ipu =
            reinterpret_cast<const ulonglong2*>(inb + (h * KPER) * R);

        #pragma unroll
        for (int kk = 0; kk < KPER; kk++) {
            float4 w = __ldg(wp + kk * (HID / 4));
            u64 wb0 = bcast2(w.x), wb1 = bcast2(w.y);
            u64 wb2 = bcast2(w.z), wb3 = bcast2(w.w);
            ulonglong2 q0 = ipu[2 * kk];       // rows (0,1),(2,3)
            ulonglong2 q1 = ipu[2 * kk + 1];   // rows (4,5),(6,7)
            acc[0][0] = ffma2(q0.x, wb0, acc[0][0]);
            acc[0][1] = ffma2(q0.x, wb1, acc[0][1]);
            acc[0][2] = ffma2(q0.x, wb2, acc[0][2]);
            acc[0][3] = ffma2(q0.x, wb3, acc[0][3]);
            acc[1][0] = ffma2(q0.y, wb0, acc[1][0]);
            acc[1][1] = ffma2(q0.y, wb1, acc[1][1]);
            acc[1][2] = ffma2(q0.y, wb2, acc[1][2]);
            acc[1][3] = ffma2(q0.y, wb3, acc[1][3]);
            acc[2][0] = ffma2(q1.x, wb0, acc[2][0]);
            acc[2][1] = ffma2(q1.x, wb1, acc[2][1]);
            acc[2][2] = ffma2(q1.x, wb2, acc[2][2]);
            acc[2][3] = ffma2(q1.x, wb3, acc[2][3]);
            acc[3][0] = ffma2(q1.y, wb0, acc[3][0]);
            acc[3][1] = ffma2(q1.y, wb1, acc[3][1]);
            acc[3][2] = ffma2(q1.y, wb2, acc[3][2]);
            acc[3][3] = ffma2(q1.y, wb3, acc[3][3]);
        }

        // store partials. u64 layout per group: idx = p*256 + col
        // (floats: rows 2p,2p+1 of col). Two STS.128 per pair, coalesced.
        {
            ulonglong2* pp = reinterpret_cast<ulonglong2*>(s_part) + h * 512;
            #pragma unroll
            for (int p = 0; p < 4; p++) {
                pp[p * 128 + 2 * c4]     = make_ulonglong2(acc[p][0], acc[p][1]);
                pp[p * 128 + 2 * c4 + 1] = make_ulonglong2(acc[p][2], acc[p][3]);
            }
        }
        __syncthreads();

        // packed reduction: thread t owns u64 slot t (rows 2p,2p+1 of col c)
        {
            const u64* sp = reinterpret_cast<const u64*>(s_part);
            u64 v = sp[t];
            #pragma unroll
            for (int g = 1; g < NG; g++) v = fadd2(v, sp[g * 1024 + t]);
            int p   = t >> 8;
            int col = t & 255;
            float lo, hi;
            unpack2(lo, hi, v);
            float bb = B[col];
            lo += bb; hi += bb;
            if (act) { lo = tanhf(lo); hi = tanhf(hi); }
            else     { lo = fmaxf(lo, 0.f); hi = fmaxf(hi, 0.f); }
            // outb transposed [col][row]; rows 2p,2p+1 contiguous
            reinterpret_cast<float2*>(outb + col * R + 2 * p)[0] =
                make_float2(lo, hi);
        }
        __syncthreads();
    };

    layer(W1, b1, bufA, bufB, 0);
    layer(W2, b2, bufB, bufA, 0);
    layer(W3, b3, bufA, bufB, 1);   // g (tanh) in bufB, transposed [col][r]

    // Epilogue: pos-neg = -0.5*iv*( xi^2 - 2*mu*xi + 2*mu*E[x2] - E[x2^2] )
    float part;
    {
        int d = t & 127;
        int r = t >> 7;
        float mu = bufB[d * R + r];
        float lv = bufB[(X2D + d) * R + r];
        float iv = __expf(-lv);
        float xi = s_x2[r * X2D + d];
        float term = xi * xi - 2.f * mu * xi + 2.f * mu * s_m[d] - s_s[d];
        part = -0.5f * iv * term;
    }
    #pragma unroll
    for (int off = 16; off > 0; off >>= 1)
        part += __shfl_xor_sync(0xffffffffu, part, off);
    if ((t & 31) == 0) s_red[t >> 5] = part;
    __syncthreads();
    if (t < 32) {
        float v = s_red[t];
        #pragma unroll
        for (int off = 16; off > 0; off >>= 1)
            v += __shfl_xor_sync(0xffffffffu, v, off);
        if (t == 0) atomicAdd(out, v * (1.0f / N_ROWS));
    }
}

// ---------------------------------------------------------------------------

extern "C" void kernel_launch(void* const* d_in, const int* in_sizes, int n_in,
                              void* d_out, int out_size)
{
    const float* x1 = (const float*)d_in[0];
    const float* x2 = (const float*)d_in[1];
    const float* W1 = (const float*)d_in[2];
    const float* b1 = (const float*)d_in[3];
    const float* W2 = (const float*)d_in[4];
    const float* b2 = (const float*)d_in[5];
    const float* W3 = (const float*)d_in[6];
    const float* b3 = (const float*)d_in[7];
    float* out = (float*)d_out;

    const int smem_bytes =
        (NG * R * HID + 2 * HID * R + R * X2D + 2 * X2D + 32) * sizeof(float);
    static int attr_set = 0;
    if (!attr_set) {
        cudaFuncSetAttribute(club_mlp_kernel,
                             cudaFuncAttributeMaxDynamicSharedMemorySize,
                             smem_bytes);
        attr_set = 1;
    }

    club_stats_kernel<<<SBLK, 1024>>>(x2, out);
    club_mlp_kernel<<<NBLK, NTHR, smem_bytes>>>(x1, x2, W1, b1, W2, b2, W3, b3, out);
}